// round 8
// baseline (speedup 1.0000x reference)
#include <cuda_runtime.h>
#include <cstdint>

// VQExpert fused kernel, round 8.
// R7 numerics (two-step z; bias-folded T) with occupancy fix: 512 threads /
// 16 warps (4 per SMSP), reg budget 128/thread. Single-buffered stripes,
// cn reloaded from smem in phase C to cut register pressure.

typedef unsigned long long ull;
#define FULLMASK 0xffffffffu

constexpr int NROW   = 500000;
constexpr int WARPS  = 16;
constexpr int RPW    = 8;
constexpr int TILE   = WARPS * RPW;              // 128
constexpr int NTILES = (NROW + TILE - 1) / TILE; // 3907

// smem layout (floats)
constexpr int O_WD2 = 0;          // 128x128: [(k>>1)*256 + j*2 + (k&1)]
constexpr int O_WP2 = 16384;      // 32x128 quad-packed: [(k>>2)*128 + c*4 + (k&3)]
constexpr int O_CB  = 20480;      // codebook quad-packed: [(d>>2)*1024 + c*4 + (d&3)]
constexpr int O_CN  = 28672;      // 256 code norms
constexpr int O_BD  = 28928;
constexpr int O_BP  = 29056;
constexpr int O_TS  = 29088;      // 16 warps x (8 rows x 128)
constexpr int SMEM_FLOATS = O_TS + WARPS * RPW * 128;   // 45472
constexpr int SMEM_BYTES  = SMEM_FLOATS * 4;            // 181,888 B

__device__ float g_T[256 * 128];   // fused codebook->output table (bias folded)

__device__ __forceinline__ ull ffma2(ull a, ull b, ull c) {
    ull d;
    asm("fma.rn.f32x2 %0, %1, %2, %3;" : "=l"(d) : "l"(a), "l"(b), "l"(c));
    return d;
}
__device__ __forceinline__ float f2sum(ull v) {
    float a, b;
    asm("mov.b64 {%0, %1}, %2;" : "=f"(a), "=f"(b) : "l"(v));
    return a + b;
}

// ---------------- prologue: build T with bias folded ----------------
__global__ void __launch_bounds__(128)
vq_precompute_kernel(const float* __restrict__ cb,
                     const float* __restrict__ Wo, const float* __restrict__ bo,
                     const float* __restrict__ Wu, const float* __restrict__ bu)
{
    __shared__ float v[128];
    const int i = threadIdx.x;
    const int c = blockIdx.x;
    float s = 0.f;
    #pragma unroll 8
    for (int d = 0; d < 32; d++) s = fmaf(cb[c * 32 + d], Wo[i * 32 + d], s);
    v[i] = s;
    __syncthreads();
    float t = 0.f, Bi = bu[i];
    #pragma unroll 8
    for (int j = 0; j < 128; j++) {
        t  = fmaf(v[j],  Wu[i * 128 + j], t);
        Bi = fmaf(bo[j], Wu[i * 128 + j], Bi);
    }
    g_T[c * 128 + i] = t + Bi;
}

// ---------------- main kernel ----------------
__global__ void __launch_bounds__(512, 1)
vq_expert_kernel(const float* __restrict__ x,
                 const float* __restrict__ Wd, const float* __restrict__ bd,
                 const float* __restrict__ Wp, const float* __restrict__ bp,
                 const float* __restrict__ cb,
                 float* __restrict__ out)
{
    extern __shared__ float sm[];
    const int tid = threadIdx.x;

    for (int i = tid; i < 128 * 128; i += 512) {
        int j = i >> 7, k = i & 127;
        sm[O_WD2 + (k >> 1) * 256 + j * 2 + (k & 1)] = Wd[i];
    }
    for (int i = tid; i < 4096; i += 512) {
        int c = i >> 7, k = i & 127;
        sm[O_WP2 + (k >> 2) * 128 + c * 4 + (k & 3)] = Wp[i];
    }
    for (int i = tid; i < 256 * 32; i += 512) {
        int c = i >> 5, d = i & 31;
        sm[O_CB + (d >> 2) * 1024 + c * 4 + (d & 3)] = cb[i];
    }
    for (int c = tid; c < 256; c += 512) {
        float s = 0.f;
        #pragma unroll 8
        for (int d = 0; d < 32; d++) { float v = cb[c * 32 + d]; s = fmaf(v, v, s); }
        sm[O_CN + c] = s;
    }
    if (tid < 128) sm[O_BD + tid] = bd[tid];
    else if (tid < 160) sm[O_BP + tid - 128] = bp[tid - 128];
    if (blockIdx.x == 0 && tid == 0)
        out[(size_t)NROW * 128 + NROW] = 0.0f;    // commit_loss == 0 exactly
    __syncthreads();

    const int wid  = tid >> 5;
    const int lane = tid & 31;
    float* myts = sm + O_TS + wid * (RPW * 128);

    const float2 bd0 = *(const float2*)(sm + O_BD + 2 * lane);
    const float2 bd1 = *(const float2*)(sm + O_BD + 64 + 2 * lane);
    const float  bpv = sm[O_BP + lane];

    float* outY = out;
    float* outI = out + (size_t)NROW * 128;

    for (int tile = blockIdx.x; tile < NTILES; tile += gridDim.x) {
        const int row0 = tile * TILE + wid * RPW;
        if (row0 >= NROW) continue;
        const bool full = (row0 + RPW <= NROW);

        // -------- stage x: 8 rows, coalesced float4 --------
        #pragma unroll
        for (int r = 0; r < RPW; r++) {
            if (full || row0 + r < NROW) {
                float4 v = ((const float4*)(x + (size_t)(row0 + r) * 128))[lane];
                ((float4*)(myts + r * 128))[lane] = v;
            }
        }
        __syncwarp();

        // -------- phase A: h = x @ Wd^T (+bd) --------
        ull acc[RPW][4];
        #pragma unroll
        for (int r = 0; r < RPW; r++)
            #pragma unroll
            for (int t = 0; t < 4; t++) acc[r][t] = 0ull;

        #pragma unroll 2
        for (int pp = 0; pp < 32; pp++) {
            const float* b0 = sm + O_WD2 + (2 * pp) * 256;
            const float* b1 = b0 + 256;
            ulonglong2 wa0 = *(const ulonglong2*)(b0 + 4 * lane);
            ulonglong2 wb0 = *(const ulonglong2*)(b0 + 128 + 4 * lane);
            ulonglong2 wa1 = *(const ulonglong2*)(b1 + 4 * lane);
            ulonglong2 wb1 = *(const ulonglong2*)(b1 + 128 + 4 * lane);
            #pragma unroll
            for (int r = 0; r < RPW; r++) {
                ulonglong2 xv = *(const ulonglong2*)(myts + r * 128 + 4 * pp);
                acc[r][0] = ffma2(xv.x, wa0.x, acc[r][0]);
                acc[r][1] = ffma2(xv.x, wa0.y, acc[r][1]);
                acc[r][2] = ffma2(xv.x, wb0.x, acc[r][2]);
                acc[r][3] = ffma2(xv.x, wb0.y, acc[r][3]);
                acc[r][0] = ffma2(xv.y, wa1.x, acc[r][0]);
                acc[r][1] = ffma2(xv.y, wa1.y, acc[r][1]);
                acc[r][2] = ffma2(xv.y, wb1.x, acc[r][2]);
                acc[r][3] = ffma2(xv.y, wb1.y, acc[r][3]);
            }
        }
        __syncwarp();
        #pragma unroll
        for (int r = 0; r < RPW; r++) {
            float2 h0, h1;
            h0.x = bd0.x + f2sum(acc[r][0]);
            h0.y = bd0.y + f2sum(acc[r][1]);
            h1.x = bd1.x + f2sum(acc[r][2]);
            h1.y = bd1.y + f2sum(acc[r][3]);
            *(float2*)(myts + r * 128 + 2 * lane) = h0;
            *(float2*)(myts + r * 128 + 64 + 2 * lane) = h1;
        }
        __syncwarp();

        // -------- phase B: z = h @ Wp^T (+bp), lane = z-column --------
        ull za[RPW];
        #pragma unroll
        for (int r = 0; r < RPW; r++) za[r] = 0ull;
        #pragma unroll 4
        for (int kq = 0; kq < 32; kq++) {
            ulonglong2 w = *(const ulonglong2*)(sm + O_WP2 + kq * 128 + 4 * lane);
            #pragma unroll
            for (int r = 0; r < RPW; r++) {
                ulonglong2 h2 = *(const ulonglong2*)(myts + r * 128 + 4 * kq);
                za[r] = ffma2(h2.x, w.x, za[r]);
                za[r] = ffma2(h2.y, w.y, za[r]);
            }
        }
        __syncwarp();
        #pragma unroll
        for (int r = 0; r < RPW; r++)
            myts[r * 128 + lane] = bpv + f2sum(za[r]);   // z in cols 0..31
        __syncwarp();

        // -------- phase C: argmin_c ||c||^2 - 2 z.c, 4 rows per pass --------
        int bc[RPW];
        #pragma unroll
        for (int hh = 0; hh < RPW / 4; hh++) {
            ull da[4][8];
            #pragma unroll
            for (int r = 0; r < 4; r++)
                #pragma unroll
                for (int i = 0; i < 8; i++) da[r][i] = 0ull;

            #pragma unroll 4
            for (int dq = 0; dq < 8; dq++) {
                ulonglong2 zq[4];
                #pragma unroll
                for (int r = 0; r < 4; r++)
                    zq[r] = *(const ulonglong2*)(myts + (hh * 4 + r) * 128 + 4 * dq);
                #pragma unroll
                for (int i = 0; i < 8; i++) {
                    ulonglong2 c2 = *(const ulonglong2*)(sm + O_CB + dq * 1024 + (i * 32 + lane) * 4);
                    #pragma unroll
                    for (int r = 0; r < 4; r++) {
                        da[r][i] = ffma2(zq[r].x, c2.x, da[r][i]);
                        da[r][i] = ffma2(zq[r].y, c2.y, da[r][i]);
                    }
                }
            }
            #pragma unroll
            for (int r = 0; r < 4; r++) {
                float bs = 3.4e38f; int bi = 0;
                #pragma unroll
                for (int i = 0; i < 8; i++) {
                    float s = sm[O_CN + i * 32 + lane] - 2.0f * f2sum(da[r][i]);
                    int c = (i << 5) | lane;
                    if (s < bs) { bs = s; bi = c; }
                }
                #pragma unroll
                for (int off = 16; off > 0; off >>= 1) {
                    float s2 = __shfl_xor_sync(FULLMASK, bs, off);
                    int   c2 = __shfl_xor_sync(FULLMASK, bi, off);
                    if (s2 < bs || (s2 == bs && c2 < bi)) { bs = s2; bi = c2; }
                }
                bc[hh * 4 + r] = bi;   // warp-uniform
            }
        }

        // -------- epilogue: y = clamp(T[bc], -1, 1) (bias pre-folded) --------
        #pragma unroll
        for (int r = 0; r < RPW; r++) {
            if (full || row0 + r < NROW) {
                float4 t = ((const float4*)(g_T + bc[r] * 128))[lane];
                float4 y;
                y.x = fminf(fmaxf(t.x, -1.0f), 1.0f);
                y.y = fminf(fmaxf(t.y, -1.0f), 1.0f);
                y.z = fminf(fmaxf(t.z, -1.0f), 1.0f);
                y.w = fminf(fmaxf(t.w, -1.0f), 1.0f);
                ((float4*)(outY + (size_t)(row0 + r) * 128))[lane] = y;
            }
        }
        if (lane == 0) {
            #pragma unroll
            for (int r = 0; r < RPW; r++)
                if (row0 + r < NROW) outI[row0 + r] = (float)bc[r];
        }
        __syncwarp();
    }
}

extern "C" void kernel_launch(void* const* d_in, const int* in_sizes, int n_in,
                              void* d_out, int out_size)
{
    const float* x  = (const float*)d_in[0];
    const float* Wd = (const float*)d_in[1];
    const float* bd = (const float*)d_in[2];
    const float* Wp = (const float*)d_in[3];
    const float* bp = (const float*)d_in[4];
    const float* cb = (const float*)d_in[5];
    const float* Wo = (const float*)d_in[6];
    const float* bo = (const float*)d_in[7];
    const float* Wu = (const float*)d_in[8];
    const float* bu = (const float*)d_in[9];
    float* out = (float*)d_out;

    cudaFuncSetAttribute(vq_expert_kernel,
                         cudaFuncAttributeMaxDynamicSharedMemorySize, SMEM_BYTES);

    vq_precompute_kernel<<<256, 128>>>(cb, Wo, bo, Wu, bu);
    vq_expert_kernel<<<148, 512, SMEM_BYTES>>>(x, Wd, bd, Wp, bp, cb, out);
}

// round 9
// speedup vs baseline: 1.0262x; 1.0262x over previous
#include <cuda_runtime.h>
#include <cstdint>

// VQExpert fused kernel, round 9.
// R8 numerics. Changes: single codebook sweep in phase C, redux-based exact
// argmin, z stored in its own smem area so the x/h stripe dies after phase B,
// enabling a cp.async prefetch of the next tile hidden under phase C.

typedef unsigned long long ull;
#define FULLMASK 0xffffffffu

constexpr int NROW   = 500000;
constexpr int WARPS  = 16;
constexpr int RPW    = 8;
constexpr int TILE   = WARPS * RPW;              // 128
constexpr int NTILES = (NROW + TILE - 1) / TILE; // 3907

// smem layout (floats)
constexpr int O_WD2 = 0;          // 128x128: [(k>>1)*256 + j*2 + (k&1)]
constexpr int O_WP2 = 16384;      // 32x128 quad-packed: [(k>>2)*128 + c*4 + (k&3)]
constexpr int O_CB  = 20480;      // codebook quad-packed: [(d>>2)*1024 + c*4 + (d&3)]
constexpr int O_CN  = 28672;      // 256 code norms
constexpr int O_BD  = 28928;
constexpr int O_BP  = 29056;
constexpr int O_TS  = 29088;      // 16 warps x (8 rows x 128)  x/h stripes
constexpr int O_ZA  = O_TS + WARPS * RPW * 128;  // 16 warps x (8 rows x 32) z
constexpr int SMEM_FLOATS = O_ZA + WARPS * RPW * 32;  // 49568
constexpr int SMEM_BYTES  = SMEM_FLOATS * 4;          // 198,272 B

__device__ float g_T[256 * 128];   // fused codebook->output table (bias folded)

__device__ __forceinline__ ull ffma2(ull a, ull b, ull c) {
    ull d;
    asm("fma.rn.f32x2 %0, %1, %2, %3;" : "=l"(d) : "l"(a), "l"(b), "l"(c));
    return d;
}
__device__ __forceinline__ float f2sum(ull v) {
    float a, b;
    asm("mov.b64 {%0, %1}, %2;" : "=f"(a), "=f"(b) : "l"(v));
    return a + b;
}
__device__ __forceinline__ void cpa16(uint32_t daddr, const void* g) {
    asm volatile("cp.async.ca.shared.global [%0], [%1], 16;" :: "r"(daddr), "l"(g));
}
__device__ __forceinline__ void cpa_commit() {
    asm volatile("cp.async.commit_group;");
}
__device__ __forceinline__ void cpa_wait0() {
    asm volatile("cp.async.wait_group 0;");
}
// monotone order-preserving float->uint key (lower float <=> lower uint)
__device__ __forceinline__ unsigned fkey(float s) {
    unsigned u = __float_as_uint(s);
    return u ^ ((u >> 31) ? 0xFFFFFFFFu : 0x80000000u);
}

// ---------------- prologue: build T with bias folded ----------------
__global__ void __launch_bounds__(128)
vq_precompute_kernel(const float* __restrict__ cb,
                     const float* __restrict__ Wo, const float* __restrict__ bo,
                     const float* __restrict__ Wu, const float* __restrict__ bu)
{
    __shared__ float v[128];
    const int i = threadIdx.x;
    const int c = blockIdx.x;
    float s = 0.f;
    #pragma unroll 8
    for (int d = 0; d < 32; d++) s = fmaf(cb[c * 32 + d], Wo[i * 32 + d], s);
    v[i] = s;
    __syncthreads();
    float t = 0.f, Bi = bu[i];
    #pragma unroll 8
    for (int j = 0; j < 128; j++) {
        t  = fmaf(v[j],  Wu[i * 128 + j], t);
        Bi = fmaf(bo[j], Wu[i * 128 + j], Bi);
    }
    g_T[c * 128 + i] = t + Bi;
}

// ---------------- main kernel ----------------
__global__ void __launch_bounds__(512, 1)
vq_expert_kernel(const float* __restrict__ x,
                 const float* __restrict__ Wd, const float* __restrict__ bd,
                 const float* __restrict__ Wp, const float* __restrict__ bp,
                 const float* __restrict__ cb,
                 float* __restrict__ out)
{
    extern __shared__ float sm[];
    const int tid = threadIdx.x;

    for (int i = tid; i < 128 * 128; i += 512) {
        int j = i >> 7, k = i & 127;
        sm[O_WD2 + (k >> 1) * 256 + j * 2 + (k & 1)] = Wd[i];
    }
    for (int i = tid; i < 4096; i += 512) {
        int c = i >> 7, k = i & 127;
        sm[O_WP2 + (k >> 2) * 128 + c * 4 + (k & 3)] = Wp[i];
    }
    for (int i = tid; i < 256 * 32; i += 512) {
        int c = i >> 5, d = i & 31;
        sm[O_CB + (d >> 2) * 1024 + c * 4 + (d & 3)] = cb[i];
    }
    for (int c = tid; c < 256; c += 512) {
        float s = 0.f;
        #pragma unroll 8
        for (int d = 0; d < 32; d++) { float v = cb[c * 32 + d]; s = fmaf(v, v, s); }
        sm[O_CN + c] = s;
    }
    if (tid < 128) sm[O_BD + tid] = bd[tid];
    else if (tid < 160) sm[O_BP + tid - 128] = bp[tid - 128];
    if (blockIdx.x == 0 && tid == 0)
        out[(size_t)NROW * 128 + NROW] = 0.0f;    // commit_loss == 0 exactly
    __syncthreads();

    const int wid  = tid >> 5;
    const int lane = tid & 31;
    float* myts = sm + O_TS + wid * (RPW * 128);
    float* myza = sm + O_ZA + wid * (RPW * 32);

    const float2 bd0 = *(const float2*)(sm + O_BD + 2 * lane);
    const float2 bd1 = *(const float2*)(sm + O_BD + 64 + 2 * lane);
    const float  bpv = sm[O_BP + lane];

    float* outY = out;
    float* outI = out + (size_t)NROW * 128;
    const int tstride = gridDim.x;

    uint32_t sb = (uint32_t)__cvta_generic_to_shared(myts + 4 * lane);

    // prefetch tile 0
    {
        int row0 = blockIdx.x * TILE + wid * RPW;
        #pragma unroll
        for (int r = 0; r < RPW; r++)
            if (row0 + r < NROW)
                cpa16(sb + r * 512, x + (size_t)(row0 + r) * 128 + 4 * lane);
        cpa_commit();
    }

    for (int tile = blockIdx.x; tile < NTILES; tile += tstride) {
        const int row0 = tile * TILE + wid * RPW;
        cpa_wait0();
        __syncwarp();
        if (row0 >= NROW) { cpa_commit(); continue; }
        const bool full = (row0 + RPW <= NROW);

        // -------- phase A: h = x @ Wd^T (+bd) --------
        ull acc[RPW][4];
        #pragma unroll
        for (int r = 0; r < RPW; r++)
            #pragma unroll
            for (int t = 0; t < 4; t++) acc[r][t] = 0ull;

        #pragma unroll 2
        for (int pp = 0; pp < 32; pp++) {
            const float* b0 = sm + O_WD2 + (2 * pp) * 256;
            const float* b1 = b0 + 256;
            ulonglong2 wa0 = *(const ulonglong2*)(b0 + 4 * lane);
            ulonglong2 wb0 = *(const ulonglong2*)(b0 + 128 + 4 * lane);
            ulonglong2 wa1 = *(const ulonglong2*)(b1 + 4 * lane);
            ulonglong2 wb1 = *(const ulonglong2*)(b1 + 128 + 4 * lane);
            #pragma unroll
            for (int r = 0; r < RPW; r++) {
                ulonglong2 xv = *(const ulonglong2*)(myts + r * 128 + 4 * pp);
                acc[r][0] = ffma2(xv.x, wa0.x, acc[r][0]);
                acc[r][1] = ffma2(xv.x, wa0.y, acc[r][1]);
                acc[r][2] = ffma2(xv.x, wb0.x, acc[r][2]);
                acc[r][3] = ffma2(xv.x, wb0.y, acc[r][3]);
                acc[r][0] = ffma2(xv.y, wa1.x, acc[r][0]);
                acc[r][1] = ffma2(xv.y, wa1.y, acc[r][1]);
                acc[r][2] = ffma2(xv.y, wb1.x, acc[r][2]);
                acc[r][3] = ffma2(xv.y, wb1.y, acc[r][3]);
            }
        }
        __syncwarp();
        #pragma unroll
        for (int r = 0; r < RPW; r++) {
            float2 h0, h1;
            h0.x = bd0.x + f2sum(acc[r][0]);
            h0.y = bd0.y + f2sum(acc[r][1]);
            h1.x = bd1.x + f2sum(acc[r][2]);
            h1.y = bd1.y + f2sum(acc[r][3]);
            *(float2*)(myts + r * 128 + 2 * lane) = h0;
            *(float2*)(myts + r * 128 + 64 + 2 * lane) = h1;
        }
        __syncwarp();

        // -------- phase B: z = h @ Wp^T (+bp), lane = z-column --------
        ull za[RPW];
        #pragma unroll
        for (int r = 0; r < RPW; r++) za[r] = 0ull;
        #pragma unroll 4
        for (int kq = 0; kq < 32; kq++) {
            ulonglong2 w = *(const ulonglong2*)(sm + O_WP2 + kq * 128 + 4 * lane);
            #pragma unroll
            for (int r = 0; r < RPW; r++) {
                ulonglong2 h2 = *(const ulonglong2*)(myts + r * 128 + 4 * kq);
                za[r] = ffma2(h2.x, w.x, za[r]);
                za[r] = ffma2(h2.y, w.y, za[r]);
            }
        }
        __syncwarp();        // all lanes done reading h -> stripe is dead
        #pragma unroll
        for (int r = 0; r < RPW; r++)
            myza[r * 32 + lane] = bpv + f2sum(za[r]);   // z to its own area
        __syncwarp();

        // prefetch NEXT tile's x into the (now dead) stripe; hidden by phase C
        {
            int nrow0 = (tile + tstride) * TILE + wid * RPW;
            #pragma unroll
            for (int r = 0; r < RPW; r++)
                if (nrow0 + r < NROW)
                    cpa16(sb + r * 512, x + (size_t)(nrow0 + r) * 128 + 4 * lane);
            cpa_commit();
        }

        // -------- phase C: argmin_c ||c||^2 - 2 z.c, single codebook sweep --------
        unsigned bkey[RPW], bidx[RPW];
        #pragma unroll
        for (int r = 0; r < RPW; r++) { bkey[r] = 0xFFFFFFFFu; bidx[r] = 0u; }

        #pragma unroll
        for (int half = 0; half < 2; half++) {
            ull da[RPW][4];
            #pragma unroll
            for (int r = 0; r < RPW; r++)
                #pragma unroll
                for (int i = 0; i < 4; i++) da[r][i] = 0ull;

            #pragma unroll 2
            for (int dq = 0; dq < 8; dq++) {
                ulonglong2 c2[4];
                #pragma unroll
                for (int i = 0; i < 4; i++)
                    c2[i] = *(const ulonglong2*)(sm + O_CB + dq * 1024
                                + ((half * 4 + i) * 32 + lane) * 4);
                #pragma unroll
                for (int rg = 0; rg < 4; rg++) {
                    ulonglong2 zq[2];
                    #pragma unroll
                    for (int r = 0; r < 2; r++)
                        zq[r] = *(const ulonglong2*)(myza + (rg * 2 + r) * 32 + 4 * dq);
                    #pragma unroll
                    for (int i = 0; i < 4; i++) {
                        #pragma unroll
                        for (int r = 0; r < 2; r++) {
                            da[rg * 2 + r][i] = ffma2(zq[r].x, c2[i].x, da[rg * 2 + r][i]);
                            da[rg * 2 + r][i] = ffma2(zq[r].y, c2[i].y, da[rg * 2 + r][i]);
                        }
                    }
                }
            }
            #pragma unroll
            for (int r = 0; r < RPW; r++) {
                #pragma unroll
                for (int i = 0; i < 4; i++) {
                    int g = half * 4 + i;
                    float s = sm[O_CN + g * 32 + lane] - 2.0f * f2sum(da[r][i]);
                    unsigned key = fkey(s);
                    if (key < bkey[r]) { bkey[r] = key; bidx[r] = (unsigned)((g << 5) | lane); }
                }
            }
        }
        int bc[RPW];
        #pragma unroll
        for (int r = 0; r < RPW; r++) {
            unsigned m = __reduce_min_sync(FULLMASK, bkey[r]);
            unsigned cand = (bkey[r] == m) ? bidx[r] : 0xFFFFFFFFu;
            bc[r] = (int)__reduce_min_sync(FULLMASK, cand);   // warp-uniform, lowest idx
        }

        // -------- epilogue: y = clamp(T[bc], -1, 1) --------
        #pragma unroll
        for (int r = 0; r < RPW; r++) {
            if (full || row0 + r < NROW) {
                float4 t = ((const float4*)(g_T + bc[r] * 128))[lane];
                float4 y;
                y.x = fminf(fmaxf(t.x, -1.0f), 1.0f);
                y.y = fminf(fmaxf(t.y, -1.0f), 1.0f);
                y.z = fminf(fmaxf(t.z, -1.0f), 1.0f);
                y.w = fminf(fmaxf(t.w, -1.0f), 1.0f);
                ((float4*)(outY + (size_t)(row0 + r) * 128))[lane] = y;
            }
        }
        if (lane == 0) {
            #pragma unroll
            for (int r = 0; r < RPW; r++)
                if (row0 + r < NROW) outI[row0 + r] = (float)bc[r];
        }
        __syncwarp();
    }
}

extern "C" void kernel_launch(void* const* d_in, const int* in_sizes, int n_in,
                              void* d_out, int out_size)
{
    const float* x  = (const float*)d_in[0];
    const float* Wd = (const float*)d_in[1];
    const float* bd = (const float*)d_in[2];
    const float* Wp = (const float*)d_in[3];
    const float* bp = (const float*)d_in[4];
    const float* cb = (const float*)d_in[5];
    const float* Wo = (const float*)d_in[6];
    const float* bo = (const float*)d_in[7];
    const float* Wu = (const float*)d_in[8];
    const float* bu = (const float*)d_in[9];
    float* out = (float*)d_out;

    cudaFuncSetAttribute(vq_expert_kernel,
                         cudaFuncAttributeMaxDynamicSharedMemorySize, SMEM_BYTES);

    vq_precompute_kernel<<<256, 128>>>(cb, Wo, bo, Wu, bu);
    vq_expert_kernel<<<148, 512, SMEM_BYTES>>>(x, Wd, bd, Wp, bp, cb, out);
}